// round 17
// baseline (speedup 1.0000x reference)
#include <cuda_runtime.h>
#include <cuda_fp16.h>
#include <math.h>
#include <stdint.h>

// Problem dims
#define BB    256
#define NA    128
#define INF   128
#define HH    256
#define G3    768
#define VV    6
#define OUTF  256
#define KFC   1536

// ---------------- scratch ----------------------------------------------------
__device__ float g_xproj[(size_t)BB * NA * G3];
__device__ float g_rnn  [(size_t)BB * NA * HH];

__global__ void k_dummy() {}

// ---------------- helpers ----------------------------------------------------
__device__ __forceinline__ uint32_t smem_u32(const void* p)
{
    uint32_t a;
    asm("{ .reg .u64 t; cvta.to.shared.u64 t, %1; cvt.u32.u64 %0, t; }" : "=r"(a) : "l"(p));
    return a;
}

__device__ __forceinline__ void mma_f16_16n8k16(float* c, uint32_t a0, uint32_t a1,
                                                uint32_t a2, uint32_t a3,
                                                uint32_t b0, uint32_t b1)
{
    asm volatile(
        "mma.sync.aligned.m16n8k16.row.col.f32.f16.f16.f32 "
        "{%0,%1,%2,%3}, {%4,%5,%6,%7}, {%8,%9}, {%0,%1,%2,%3};"
        : "+f"(c[0]), "+f"(c[1]), "+f"(c[2]), "+f"(c[3])
        : "r"(a0), "r"(a1), "r"(a2), "r"(a3), "r"(b0), "r"(b1));
}

// async DSMEM b32 store with tx credit to remote mbarrier
__device__ __forceinline__ void st_async_u32(uint32_t laddr, uint32_t lmbar,
                                             uint32_t rank, uint32_t v)
{
    uint32_t ra, rm;
    asm volatile("mapa.shared::cluster.u32 %0, %1, %2;" : "=r"(ra) : "r"(laddr), "r"(rank));
    asm volatile("mapa.shared::cluster.u32 %0, %1, %2;" : "=r"(rm) : "r"(lmbar), "r"(rank));
    asm volatile("st.async.shared::cluster.mbarrier::complete_tx::bytes.b32 [%0], %1, [%2];"
                 :: "r"(ra), "r"(v), "r"(rm) : "memory");
}

#define MBAR_INIT(addr, cnt) \
    asm volatile("mbarrier.init.shared.b64 [%0], %1;" :: "r"(addr), "r"(cnt) : "memory")

#define MBAR_EXPECT_TX(addr, n) \
    asm volatile("mbarrier.arrive.expect_tx.shared.b64 _, [%0], %1;" :: "r"(addr), "r"(n) : "memory")

#define MBAR_SPIN(addr, par) do {                                              \
    uint32_t _m = (addr), _p = (par), _d = 0;                                  \
    while (!_d) {                                                              \
        asm volatile("{\n\t.reg .pred p;\n\t"                                  \
            "mbarrier.test_wait.parity.acquire.cluster.shared::cta.b64 p, [%1], %2;\n\t" \
            "selp.b32 %0, 1, 0, p;\n\t}"                                       \
            : "=r"(_d) : "r"(_m), "r"(_p) : "memory");                         \
    }                                                                          \
} while (0)

// pack 8 consecutive floats -> 4 half2 words
__device__ __forceinline__ uint4 pack8h(const float* p)
{
    float4 v0 = *(const float4*)p;
    float4 v1 = *(const float4*)(p + 4);
    __half2 h0 = __floats2half2_rn(v0.x, v0.y);
    __half2 h1 = __floats2half2_rn(v0.z, v0.w);
    __half2 h2 = __floats2half2_rn(v1.x, v1.y);
    __half2 h3 = __floats2half2_rn(v1.z, v1.w);
    return make_uint4(*(uint32_t*)&h0, *(uint32_t*)&h1,
                      *(uint32_t*)&h2, *(uint32_t*)&h3);
}

// ============================================================================
// fp16 warp-mma GEMM: C[128,128] tiles, 8 warps 2x4, m16n8k16, K-chunk 64.
// SMEM [row][word] (word = half2, k-pair), stride 36 -> conflict-free frags.
// Fragment layout validated in R15's GRU (same word mapping).
// ============================================================================

__global__ __launch_bounds__(256, 2)
void k_xproj_mma(const float* __restrict__ X, const float* __restrict__ Wih,
                 const float* __restrict__ bias)
{
    __shared__ uint32_t As[128][36];
    __shared__ uint32_t Ws[128][36];

    const int tid = threadIdx.x, lane = tid & 31, wid = tid >> 5;
    const int warpM = wid >> 2, warpN = wid & 3;
    const int b = blockIdx.y, n0 = blockIdx.x * 128;
    const int g = lane >> 2, q = lane & 3;

    float acc[4][4][4];
#pragma unroll
    for (int i = 0; i < 4; i++)
#pragma unroll
        for (int j = 0; j < 4; j++)
#pragma unroll
            for (int r = 0; r < 4; r++) acc[i][j][r] = 0.f;

    for (int c = 0; c < INF / 64; c++) {           // 2 chunks of K=64
        const int k0 = c * 64;
#pragma unroll
        for (int l = 0; l < 4; l++) {
            int f = tid + l * 256;                 // 0..1023
            int row = f >> 3, c8 = f & 7;          // 8 halves per task
            *(uint4*)&As[row][c8 * 4] =
                pack8h(X + ((size_t)b * NA + row) * INF + k0 + c8 * 8);
            *(uint4*)&Ws[row][c8 * 4] =
                pack8h(Wih + (size_t)(n0 + row) * INF + k0 + c8 * 8);
        }
        __syncthreads();
#pragma unroll
        for (int ks = 0; ks < 4; ks++) {           // 4 k16-steps
            uint32_t bf[4][2];
#pragma unroll
            for (int nt = 0; nt < 4; nt++) {
                int nb = warpN * 32 + nt * 8 + g;
                bf[nt][0] = Ws[nb][ks * 8 + q];
                bf[nt][1] = Ws[nb][ks * 8 + q + 4];
            }
#pragma unroll
            for (int mt = 0; mt < 4; mt++) {
                int mb = warpM * 64 + mt * 16 + g;
                uint32_t a0 = As[mb][ks * 8 + q];
                uint32_t a1 = As[mb + 8][ks * 8 + q];
                uint32_t a2 = As[mb][ks * 8 + q + 4];
                uint32_t a3 = As[mb + 8][ks * 8 + q + 4];
#pragma unroll
                for (int nt = 0; nt < 4; nt++)
                    mma_f16_16n8k16(acc[mt][nt], a0, a1, a2, a3, bf[nt][0], bf[nt][1]);
            }
        }
        __syncthreads();
    }

#pragma unroll
    for (int mt = 0; mt < 4; mt++) {
#pragma unroll
        for (int nt = 0; nt < 4; nt++) {
            int mrow = warpM * 64 + mt * 16 + g;
            int ncol = n0 + warpN * 32 + nt * 8 + 2 * q;
            float b0 = __ldg(bias + ncol), b1 = __ldg(bias + ncol + 1);
            float* o = g_xproj + ((size_t)b * NA + mrow) * G3 + ncol;
            *(float2*)o = make_float2(acc[mt][nt][0] + b0, acc[mt][nt][1] + b1);
            float* o2 = o + 8 * G3;
            *(float2*)o2 = make_float2(acc[mt][nt][2] + b0, acc[mt][nt][3] + b1);
        }
    }
}

__global__ __launch_bounds__(256, 2)
void k_fc_mma(const int* __restrict__ bonded, const float* __restrict__ Wfc,
              const float* __restrict__ bfc, float* __restrict__ Out)
{
    __shared__ uint32_t As[128][36];
    __shared__ uint32_t Ws[128][36];
    __shared__ int idx_s[NA * VV];

    const int tid = threadIdx.x, lane = tid & 31, wid = tid >> 5;
    const int warpM = wid >> 2, warpN = wid & 3;
    const int b = blockIdx.y, n0 = blockIdx.x * 128;
    const int g = lane >> 2, q = lane & 3;

    for (int i = tid; i < NA * VV; i += 256)
        idx_s[i] = bonded[(size_t)b * NA * VV + i];

    float acc[4][4][4];
#pragma unroll
    for (int i = 0; i < 4; i++)
#pragma unroll
        for (int j = 0; j < 4; j++)
#pragma unroll
            for (int r = 0; r < 4; r++) acc[i][j][r] = 0.f;

    const float* rnn_b = g_rnn + (size_t)b * NA * HH;
    __syncthreads();

    for (int c = 0; c < KFC / 64; c++) {           // 24 chunks of K=64
        const int v = c >> 2, hsub = (c & 3) * 64, k0 = c * 64;
#pragma unroll
        for (int l = 0; l < 4; l++) {
            int f = tid + l * 256;
            int row = f >> 3, c8 = f & 7;
            *(uint4*)&As[row][c8 * 4] =
                pack8h(rnn_b + (size_t)idx_s[row * VV + v] * HH + hsub + c8 * 8);
            *(uint4*)&Ws[row][c8 * 4] =
                pack8h(Wfc + (size_t)(n0 + row) * KFC + k0 + c8 * 8);
        }
        __syncthreads();
#pragma unroll
        for (int ks = 0; ks < 4; ks++) {
            uint32_t bf[4][2];
#pragma unroll
            for (int nt = 0; nt < 4; nt++) {
                int nb = warpN * 32 + nt * 8 + g;
                bf[nt][0] = Ws[nb][ks * 8 + q];
                bf[nt][1] = Ws[nb][ks * 8 + q + 4];
            }
#pragma unroll
            for (int mt = 0; mt < 4; mt++) {
                int mb = warpM * 64 + mt * 16 + g;
                uint32_t a0 = As[mb][ks * 8 + q];
                uint32_t a1 = As[mb + 8][ks * 8 + q];
                uint32_t a2 = As[mb][ks * 8 + q + 4];
                uint32_t a3 = As[mb + 8][ks * 8 + q + 4];
#pragma unroll
                for (int nt = 0; nt < 4; nt++)
                    mma_f16_16n8k16(acc[mt][nt], a0, a1, a2, a3, bf[nt][0], bf[nt][1]);
            }
        }
        __syncthreads();
    }

#pragma unroll
    for (int mt = 0; mt < 4; mt++) {
#pragma unroll
        for (int nt = 0; nt < 4; nt++) {
            int mrow = warpM * 64 + mt * 16 + g;
            int ncol = n0 + warpN * 32 + nt * 8 + 2 * q;
            float b0 = __ldg(bfc + ncol), b1 = __ldg(bfc + ncol + 1);
            float y0 = acc[mt][nt][0] + b0, y1 = acc[mt][nt][1] + b1;
            float y2 = acc[mt][nt][2] + b0, y3 = acc[mt][nt][3] + b1;
            y0 = y0 >= 0.f ? y0 : 0.1f * y0;
            y1 = y1 >= 0.f ? y1 : 0.1f * y1;
            y2 = y2 >= 0.f ? y2 : 0.1f * y2;
            y3 = y3 >= 0.f ? y3 : 0.1f * y3;
            float* o = Out + ((size_t)b * NA + mrow) * OUTF + ncol;
            *(float2*)o = make_float2(y0, y1);
            *(float2*)(o + 8 * OUTF) = make_float2(y2, y3);
        }
    }
}

// ============================================================================
// GRU v8 (R15, unchanged): 64 clusters x 2 CTAs x 256 thr. Cluster owns 4
// batches; CTA rank owns j in [128r, 128r+128). W fp16 in SMEM; h state fp32
// in regs, fp16 on the wire. Exchange fan-out = 1 peer (+self), TX=2048B.
// ============================================================================
#define WROW     132
#define W_WORDS  (384 * WROW)
#define H_PAR    (4 * WROW)
#define H_OFF    W_WORDS
#define MB_OFF   (H_OFF + 2 * H_PAR)
#define GRU_SMEM ((MB_OFF + 4) * 4)
#define TX_BYTES 2048u

__global__ void __cluster_dims__(2, 1, 1) __launch_bounds__(256, 1)
k_gru_mma(const float* __restrict__ W_hh, const float* __restrict__ b_hh)
{
    extern __shared__ uint32_t smg[];
    uint32_t* Wsm = smg;
    uint32_t* hin = smg + H_OFF;

    const int tid = threadIdx.x, lane = tid & 31, w = tid >> 5;
    const int g = lane >> 2, q = lane & 3;
    uint32_t rank;
    asm("mov.u32 %0, %%cluster_ctarank;" : "=r"(rank));
    const int b0c  = (blockIdx.x >> 1) * 4;
    const int bat  = g & 3;
    const bool fin = (g < 4);
    const int myb  = b0c + bat;
    const int jbase = (int)rank * 128 + w * 16 + 2 * q;

    const uint32_t sbase   = smem_u32(smg);
    const uint32_t hin_addr = sbase + H_OFF * 4u;
    const uint32_t mb_base  = sbase + MB_OFF * 4u;

    for (int i = tid; i < 384 * 128; i += 256) {
        int r = i >> 7, kw = i & 127;
        int gate = r >> 7, jl = r & 127;
        float2 v = *(const float2*)(W_hh +
            ((size_t)(gate * 256 + (int)rank * 128 + jl)) * 256 + kw * 2);
        __half2 h2 = __floats2half2_rn(v.x, v.y);
        Wsm[(size_t)r * WROW + kw] = *(uint32_t*)&h2;
    }
    for (int i = tid; i < 2 * H_PAR; i += 256) hin[i] = 0u;
    if (tid == 0) {
        MBAR_INIT(mb_base + 0u, 1);
        MBAR_INIT(mb_base + 8u, 1);
        MBAR_EXPECT_TX(mb_base + 0u, TX_BYTES);
        MBAR_EXPECT_TX(mb_base + 8u, TX_BYTES);
    }
    __syncthreads();
    asm volatile("barrier.cluster.arrive.aligned;" ::: "memory");
    asm volatile("barrier.cluster.wait.aligned;" ::: "memory");

    float2 brv[2], bzv[2], bnv[2];
#pragma unroll
    for (int nt = 0; nt < 2; nt++) {
        brv[nt] = *(const float2*)(b_hh + jbase + nt * 8);
        bzv[nt] = *(const float2*)(b_hh + 256 + jbase + nt * 8);
        bnv[nt] = *(const float2*)(b_hh + 512 + jbase + nt * 8);
    }

    const uint32_t* WB[3][2];
#pragma unroll
    for (int gate = 0; gate < 3; gate++)
#pragma unroll
        for (int nt = 0; nt < 2; nt++)
            WB[gate][nt] = Wsm + (size_t)(gate * 128 + w * 16 + nt * 8 + g) * WROW;

    float hp[2][2] = {{0.f, 0.f}, {0.f, 0.f}};

    for (int t = 0; t < NA; t++) {
        const int buf = t & 1;
        const uint32_t cur_mb = mb_base + (uint32_t)buf * 8u;
        const uint32_t* hc = hin + buf * H_PAR;

        if (t >= 1) {
            MBAR_SPIN(cur_mb, ((t - 1) >> 1) & 1);
            if (tid == 0) MBAR_EXPECT_TX(cur_mb, TX_BYTES);
        }

        float2 xr[2], xz[2], xn[2];
        if (fin) {
            const float* xp = g_xproj + ((size_t)myb * NA + t) * G3 + jbase;
#pragma unroll
            for (int nt = 0; nt < 2; nt++) {
                xr[nt] = __ldg((const float2*)(xp + nt * 8));
                xz[nt] = __ldg((const float2*)(xp + 256 + nt * 8));
                xn[nt] = __ldg((const float2*)(xp + 512 + nt * 8));
            }
        }

        float acc[3][2][4];
#pragma unroll
        for (int gate = 0; gate < 3; gate++)
#pragma unroll
            for (int nt = 0; nt < 2; nt++)
#pragma unroll
                for (int r = 0; r < 4; r++) acc[gate][nt][r] = 0.f;

        const uint32_t* hrow = hc + bat * WROW;
#pragma unroll
        for (int ks = 0; ks < 16; ks++) {
            uint32_t a0 = hrow[ks * 8 + q];
            uint32_t a2 = hrow[ks * 8 + q + 4];
#pragma unroll
            for (int gate = 0; gate < 3; gate++)
#pragma unroll
                for (int nt = 0; nt < 2; nt++) {
                    uint32_t bb0 = WB[gate][nt][ks * 8 + q];
                    uint32_t bb1 = WB[gate][nt][ks * 8 + q + 4];
                    mma_f16_16n8k16(acc[gate][nt], a0, a0, a2, a2, bb0, bb1);
                }
        }

        if (fin) {
#pragma unroll
            for (int nt = 0; nt < 2; nt++) {
                float sR0 = acc[0][nt][0], sR1 = acc[0][nt][1];
                float sZ0 = acc[1][nt][0], sZ1 = acc[1][nt][1];
                float sN0 = acc[2][nt][0], sN1 = acc[2][nt][1];

                float r0 = 1.f / (1.f + __expf(-(xr[nt].x + sR0 + brv[nt].x)));
                float r1 = 1.f / (1.f + __expf(-(xr[nt].y + sR1 + brv[nt].y)));
                float z0 = 1.f / (1.f + __expf(-(xz[nt].x + sZ0 + bzv[nt].x)));
                float z1 = 1.f / (1.f + __expf(-(xz[nt].y + sZ1 + bzv[nt].y)));
                float n0 = tanhf(xn[nt].x + r0 * (sN0 + bnv[nt].x));
                float n1 = tanhf(xn[nt].y + r1 * (sN1 + bnv[nt].y));
                float h0 = (1.f - z0) * n0 + z0 * hp[nt][0];
                float h1 = (1.f - z1) * n1 + z1 * hp[nt][1];
                hp[nt][0] = h0; hp[nt][1] = h1;

                *(float2*)(g_rnn + ((size_t)myb * NA + t) * HH + jbase + nt * 8) =
                    make_float2(h0, h1);

                if (t < NA - 1) {
                    const int nbuf = (t + 1) & 1;
                    __half2 p = __floats2half2_rn(h0, h1);
                    uint32_t pv = *(uint32_t*)&p;
                    uint32_t word = (uint32_t)(bat * WROW +
                        ((int)rank * 64 + w * 8 + nt * 4 + q));
                    uint32_t laddr = hin_addr + (uint32_t)(nbuf * H_PAR) * 4u + word * 4u;
                    uint32_t lmbar = mb_base + (uint32_t)nbuf * 8u;
                    st_async_u32(laddr, lmbar, rank, pv);        // self
                    st_async_u32(laddr, lmbar, rank ^ 1u, pv);   // peer
                }
            }
        }
    }
}

// ---------------- launch ------------------------------------------------------
extern "C" void kernel_launch(void* const* d_in, const int* in_sizes, int n_in,
                              void* d_out, int out_size)
{
    const float* x      = (const float*)d_in[0];
    const int*   bonded = (const int*)  d_in[1];
    const float* W_ih   = (const float*)d_in[2];
    const float* W_hh   = (const float*)d_in[3];
    const float* b_ih   = (const float*)d_in[4];
    const float* b_hh   = (const float*)d_in[5];
    const float* W_fc   = (const float*)d_in[6];
    const float* b_fc   = (const float*)d_in[7];
    float* out = (float*)d_out;

    cudaFuncSetAttribute(k_gru_mma,
                         cudaFuncAttributeMaxDynamicSharedMemorySize, GRU_SMEM);

    // one dummy: aims the profiled slot at the FC kernel this round
    k_dummy<<<1, 32>>>();

    // 1) x_proj (fp16 mma)
    k_xproj_mma<<<dim3(G3 / 128, BB), 256>>>(x, W_ih, b_ih);

    // 2) GRU: 2-CTA clusters (fan-out 1), fp16 W/h wire, fp32 state
    k_gru_mma<<<128, 256, GRU_SMEM>>>(W_hh, b_hh);

    // 3) FC (fp16 mma, gather fused)
    k_fc_mma<<<dim3(OUTF / 128, BB), 256>>>(bonded, W_fc, b_fc, out);
}